// round 14
// baseline (speedup 1.0000x reference)
#include <cuda_runtime.h>
#include <cuda.h>
#include <math.h>
#include <stdint.h>

// SRBGCN: 2-layer hyperbolic GCN.
// gemm0: tf32 TMA GEMM on fp32 adj (BM=64, 2 CTA/SM); re-encodes adj as s8
//        fixed-point (scale 127*16384, cancels in Minkowski normalization),
//        encode placed AFTER the next TMA issue so the copy engine never
//        waits on F2I work; epilogue: normalize+selu+Poincare + M1 +
//        msg1(fp32) + col absmax.
// quant: msg1 fp32 -> s8, per-column scale.
// gemm1: int8 TMA GEMM (m16n8k32 s8), BK=256/stage so only 64 sync points
//        (QMMA-pipe-bound; fewer syncs -> higher tensor util), 2 CTA/SM,
//        per-column dequant + final epilogue.

constexpr int NN     = 16384;
constexpr int D      = 32;
constexpr int BM     = 64;                 // rows per CTA (both gemms)

// ---- gemm0 (fp32) pipeline ----
constexpr int BK       = 64;
constexpr int STAGES   = 4;
constexpr int NITER    = NN / BK;          // 256
constexpr int ADJ_CH_B = 32 * BM * 4;      // 8192
constexpr int MSG_CH_B = 32 * 32 * 4;      // 4096
constexpr int STAGE_B  = 2 * ADJ_CH_B + 2 * MSG_CH_B;  // 24576
constexpr int DYN_B    = STAGES * STAGE_B + 1024;      // 99328 -> 2 CTA/SM

// ---- gemm1 (int8) pipeline ----
constexpr int BK1      = 256;              // k per stage (2 x 128-col boxes)
constexpr int STAGES1  = 3;
constexpr int NITER1   = NN / BK1;         // 64
constexpr int ADJ8_CH  = BM * 128;         // 8192 per 128-col chunk
constexpr int MSG8_CH  = 32 * 128;         // 4096 per 128-col chunk
constexpr int STAGE1_B = 2 * ADJ8_CH + 2 * MSG8_CH;    // 24576
constexpr int DYN1_B   = STAGES1 * STAGE1_B + 1024;    // 74752 -> 2 CTA/SM

constexpr float S_A = 127.0f * 16384.0f;   // adj fixed-point scale (cancels)

// Scratch (static device arrays; no allocation allowed)
__device__ __align__(1024) float    g_msgT[D * NN];           // fp32 msg0 [n][k]
__device__ __align__(1024) float    g_msgT1[D * NN];          // fp32 msg1 [n][k]
__device__ __align__(1024) uint8_t  g_adj8[(size_t)NN * NN];  // s8 adj (0..127)
__device__ __align__(1024) uint8_t  g_msg8[(size_t)D * NN];   // s8 msg1 [n][k]
__device__ unsigned g_colmax[D];

// ---------------------------------------------------------------------------
__device__ __forceinline__ uint32_t smem_u32(const void* p) {
    return (uint32_t)__cvta_generic_to_shared(p);
}
__device__ __forceinline__ void mma_tf32(float* c,
                                         uint32_t a0, uint32_t a1, uint32_t a2, uint32_t a3,
                                         uint32_t b0, uint32_t b1) {
    asm volatile(
        "mma.sync.aligned.m16n8k8.row.col.f32.tf32.tf32.f32 "
        "{%0,%1,%2,%3}, {%4,%5,%6,%7}, {%8,%9}, {%0,%1,%2,%3};"
        : "+f"(c[0]), "+f"(c[1]), "+f"(c[2]), "+f"(c[3])
        : "r"(a0), "r"(a1), "r"(a2), "r"(a3), "r"(b0), "r"(b1));
}
__device__ __forceinline__ void mma_s8(int* c,
                                       uint32_t a0, uint32_t a1, uint32_t a2, uint32_t a3,
                                       uint32_t b0, uint32_t b1) {
    asm volatile(
        "mma.sync.aligned.m16n8k32.row.col.s32.s8.s8.s32 "
        "{%0,%1,%2,%3}, {%4,%5,%6,%7}, {%8,%9}, {%0,%1,%2,%3};"
        : "+r"(c[0]), "+r"(c[1]), "+r"(c[2]), "+r"(c[3])
        : "r"(a0), "r"(a1), "r"(a2), "r"(a3), "r"(b0), "r"(b1));
}
__device__ __forceinline__ void mbar_init(uint32_t mbar, uint32_t cnt) {
    asm volatile("mbarrier.init.shared.b64 [%0], %1;" :: "r"(mbar), "r"(cnt) : "memory");
}
__device__ __forceinline__ void mbar_expect_tx(uint32_t mbar, uint32_t bytes) {
    asm volatile("mbarrier.arrive.expect_tx.shared.b64 _, [%0], %1;"
                 :: "r"(mbar), "r"(bytes) : "memory");
}
__device__ __forceinline__ void mbar_wait(uint32_t mbar, uint32_t parity) {
    asm volatile(
        "{\n\t.reg .pred P1;\n\t"
        "WAIT_LOOP_%=:\n\t"
        "mbarrier.try_wait.parity.shared.b64 P1, [%0], %1;\n\t"
        "@P1 bra.uni WAIT_DONE_%=;\n\t"
        "bra.uni WAIT_LOOP_%=;\n\t"
        "WAIT_DONE_%=:\n\t}"
        :: "r"(mbar), "r"(parity) : "memory");
}
__device__ __forceinline__ void tma_load_2d(uint32_t smem_dst, const void* map,
                                            int cx, int cy, uint32_t mbar) {
    asm volatile(
        "cp.async.bulk.tensor.2d.shared::cta.global.tile.mbarrier::complete_tx::bytes "
        "[%0], [%1, {%2, %3}], [%4];"
        :: "r"(smem_dst), "l"(map), "r"(cx), "r"(cy), "r"(mbar) : "memory");
}
__device__ __forceinline__ float lwh_elem(int i, int j, const float* h,
                                          float ch, float sh, float invn) {
    float ni = (i >= 1) ? h[i] * invn : 0.f;
    float nj = (j >= 1) ? h[j] * invn : 0.f;
    if (i == 0 && j == 0) return ch;
    if (i == 0)           return sh * nj;
    if (j == 0)           return sh * ni;
    return ((i == j) ? 1.f : 0.f) - (1.f - ch) * ni * nj;
}

// ---------------------------------------------------------------------------
// Kernel 1: msgT0. Also zeroes g_colmax (block 0).
// ---------------------------------------------------------------------------
__global__ __launch_bounds__(1024)
void msgT0_kernel(const float* __restrict__ node,
                  const float* __restrict__ Ws,
                  const float* __restrict__ Hs) {
    __shared__ float Wsm[961];
    __shared__ float hsm[32];
    __shared__ float sc[3];
    __shared__ float LWh[1024];
    __shared__ float Ms[1024];
    __shared__ float xs[128][33];
    __shared__ float ot[32][129];

    const int tid = threadIdx.x;
    const int r0  = blockIdx.x * 128;

    if (blockIdx.x == 0 && tid < 32) g_colmax[tid] = 0u;

    if (tid < 961) Wsm[tid] = Ws[tid];
    if (tid < 32)  hsm[tid] = Hs[tid];
    {
        int r  = tid >> 3;
        int c4 = tid & 7;
        float4 v = *reinterpret_cast<const float4*>(node + (size_t)(r0 + r) * D + c4 * 4);
        xs[r][c4 * 4 + 0] = v.x;
        xs[r][c4 * 4 + 1] = v.y;
        xs[r][c4 * 4 + 2] = v.z;
        xs[r][c4 * 4 + 3] = v.w;
    }
    __syncthreads();

    if (tid == 0) {
        float ss = 0.f;
        for (int t = 1; t < 32; t++) { float v = hsm[t]; ss += v * v; }
        sc[0] = coshf(hsm[0]);
        sc[1] = sinhf(hsm[0]);
        sc[2] = rsqrtf(ss + 1e-14f);
    }
    __syncthreads();

    LWh[tid] = lwh_elem(tid >> 5, tid & 31, hsm, sc[0], sc[1], sc[2]);
    __syncthreads();

    {
        int i = tid >> 5, j = tid & 31;
        float m;
        if (i == 0) {
            m = LWh[j];
        } else {
            m = 0.f;
#pragma unroll
            for (int k = 1; k < 32; k++)
                m += Wsm[(k - 1) * 31 + (i - 1)] * LWh[k * 32 + j];
        }
        Ms[tid] = m;
    }
    __syncthreads();

    {
        const int n  = tid & 31;
        const int rg = tid >> 5;
#pragma unroll
        for (int rr = 0; rr < 4; rr++) {
            const int r = rg * 4 + rr;
            float acc = 0.f;
#pragma unroll
            for (int k = 0; k < 32; k++)
                acc = fmaf(xs[r][k], Ms[k * 32 + n], acc);
            ot[n][r] = acc;
        }
    }
    __syncthreads();

#pragma unroll
    for (int u = 0; u < 4; u++) {
        int idx = u * 1024 + tid;
        int n   = idx >> 7;
        int r   = idx & 127;
        g_msgT[(size_t)n * NN + r0 + r] = ot[n][r];
    }
}

// ---------------------------------------------------------------------------
// Kernel 2 (gemm0): tf32 GEMM (BM=64, 8 warps 4m x 2n) + s8 re-encode of adj
// placed after TMA issue + fused epilogue -> msg1 fp32 + col absmax.
// ---------------------------------------------------------------------------
__global__ __launch_bounds__(256)
void gemm0_kernel(const __grid_constant__ CUtensorMap tma_adj,
                  const __grid_constant__ CUtensorMap tma_msg,
                  const float* __restrict__ Ws,
                  const float* __restrict__ Hs) {
    extern __shared__ float dsm[];
    __shared__ alignas(8) uint64_t full_bar[STAGES];
    __shared__ float sc[3];

    const int tid  = threadIdx.x;
    const int lane = tid & 31;
    const int w    = tid >> 5;     // 0..7
    const int wm   = w & 3;        // m group
    const int wn   = w >> 2;       // n group
    const int g    = lane >> 2;    // 0..7
    const int c    = lane & 3;     // 0..3
    const int row0 = blockIdx.x * BM;

    const uint32_t sb    = smem_u32(dsm);
    const uint32_t base0 = (sb + 1023u) & ~1023u;
    char* tiles = (char*)dsm + (base0 - sb);

    if (tid == 0) {
#pragma unroll
        for (int s = 0; s < STAGES; s++)
            mbar_init(smem_u32(&full_bar[s]), 1u);
    }
    __syncthreads();
    if (tid == 0)
        asm volatile("fence.proxy.async.shared::cta;" ::: "memory");

    auto issue_stage = [&](int j) {
        const int  slot = j % STAGES;
        const int  kt   = j * BK;
        const uint32_t mb = smem_u32(&full_bar[slot]);
        const uint32_t db = base0 + (uint32_t)(slot * STAGE_B);
        mbar_expect_tx(mb, (uint32_t)STAGE_B);
        tma_load_2d(db,                           &tma_adj, kt,      row0, mb);
        tma_load_2d(db + ADJ_CH_B,                &tma_adj, kt + 32, row0, mb);
        tma_load_2d(db + 2 * ADJ_CH_B,            &tma_msg, kt,      0,    mb);
        tma_load_2d(db + 2 * ADJ_CH_B + MSG_CH_B, &tma_msg, kt + 32, 0,    mb);
    };

    if (tid == 0) {
#pragma unroll
        for (int j = 0; j < STAGES - 1; j++) issue_stage(j);
    }

    float acc[2][4];
#pragma unroll
    for (int nt = 0; nt < 2; nt++)
#pragma unroll
        for (int j = 0; j < 4; j++) acc[nt][j] = 0.f;

    const int r0 = wm * 16 + g;
    const int r1 = r0 + 8;

    // re-encode thread mapping (conflict-free LDS)
    const int qe_h    = tid >> 7;          // 0..1 chunk
    const int qe_r    = (tid & 127) >> 1;  // 0..63 row
    const int qe_half = tid & 1;           // 0..1

    for (int it = 0; it < NITER; it++) {
        const int slot = it % STAGES;
        mbar_wait(smem_u32(&full_bar[slot]), (uint32_t)((it / STAGES) & 1));

        const char* stg = tiles + slot * STAGE_B;
#pragma unroll
        for (int ks = 0; ks < 8; ks++) {
            const float* Ah = (const float*)(stg + (ks >> 2) * ADJ_CH_B);
            const float* Bh = (const float*)(stg + 2 * ADJ_CH_B + (ks >> 2) * MSG_CH_B);
            const int u0 = (ks & 3) * 2;

            uint32_t a0 = __float_as_uint(Ah[r0 * 32 + ((u0    ) ^ g) * 4 + c]);
            uint32_t a1 = __float_as_uint(Ah[r1 * 32 + ((u0    ) ^ g) * 4 + c]);
            uint32_t a2 = __float_as_uint(Ah[r0 * 32 + ((u0 + 1) ^ g) * 4 + c]);
            uint32_t a3 = __float_as_uint(Ah[r1 * 32 + ((u0 + 1) ^ g) * 4 + c]);
#pragma unroll
            for (int nt = 0; nt < 2; nt++) {
                const int n = wn * 16 + nt * 8 + g;
                uint32_t b0 = __float_as_uint(Bh[n * 32 + ((u0    ) ^ g) * 4 + c]);
                uint32_t b1 = __float_as_uint(Bh[n * 32 + ((u0 + 1) ^ g) * 4 + c]);
                mma_tf32(acc[nt], a0, a1, a2, a3, b0, b1);
            }
        }

        // sync first: all consumers of the OLDEST slot (mma it-? and encode
        // it-1, which ran after the previous sync) are done -> safe to issue.
        __syncthreads();
        const int nj = it + STAGES - 1;
        if (tid == 0 && nj < NITER) issue_stage(nj);   // overwrites slot (it-1)%S

        // ---- s8 re-encode slot it (runs while TMA streams) -----------------
        {
            const float* ch = (const float*)(stg + qe_h * ADJ_CH_B);
            uint32_t b[4];
#pragma unroll
            for (int i = 0; i < 4; i++) {
                const int u = qe_half * 4 + i;
                const float4 v = *(const float4*)(ch + (qe_r * 8 + (u ^ (qe_r & 7))) * 4);
                uint32_t q0 = __float2uint_rn(v.x * S_A);
                uint32_t q1 = __float2uint_rn(v.y * S_A);
                uint32_t q2 = __float2uint_rn(v.z * S_A);
                uint32_t q3 = __float2uint_rn(v.w * S_A);
                b[i] = q0 | (q1 << 8) | (q2 << 16) | (q3 << 24);
            }
            uint8_t* dst = g_adj8 + (size_t)(row0 + qe_r) * NN + (size_t)it * BK
                         + qe_h * 32 + qe_half * 16;
            *reinterpret_cast<uint4*>(dst) = make_uint4(b[0], b[1], b[2], b[3]);
        }
    }

    // ---- epilogue smem ----------------------------------------------------
    __syncthreads();
    float* sup  = (float*)tiles;          // 64 x 33
    float* sup2 = sup  + 64 * 33;         // 64 x 33 (W1 staging then msg1)
    float* LWh  = sup2 + 64 * 33;         // 32 x 32 (later colmax staging)
    float* Ms   = LWh  + 1024;            // 32 x 32

#pragma unroll
    for (int nt = 0; nt < 2; nt++) {
        int cb = wn * 16 + nt * 8 + 2 * c;
        sup[r0 * 33 + cb]     = acc[nt][0];
        sup[r0 * 33 + cb + 1] = acc[nt][1];
        sup[r1 * 33 + cb]     = acc[nt][2];
        sup[r1 * 33 + cb + 1] = acc[nt][3];
    }

    // ---- build M1 (W1 staged in smem) ---------------------------------------
    {
        const float* W1 = Ws + 31 * 31;
        const float* h1 = Hs + 32;
        float* Wsm = sup2;
#pragma unroll
        for (int u = 0; u < 4; u++) {
            int idx = u * 256 + tid;
            if (idx < 961) Wsm[idx] = W1[idx];
        }
        if (tid == 0) {
            float ss = 0.f;
            for (int t = 1; t < 32; t++) { float v = h1[t]; ss += v * v; }
            sc[0] = coshf(h1[0]);
            sc[1] = sinhf(h1[0]);
            sc[2] = rsqrtf(ss + 1e-14f);
        }
        __syncthreads();
#pragma unroll
        for (int u = 0; u < 4; u++) {
            int idx = u * 256 + tid;
            LWh[idx] = lwh_elem(idx >> 5, idx & 31, h1, sc[0], sc[1], sc[2]);
        }
        __syncthreads();
#pragma unroll
        for (int u = 0; u < 4; u++) {
            int idx = u * 256 + tid;
            int i = idx >> 5, j = idx & 31;
            float m;
            if (i == 0) {
                m = LWh[j];
            } else {
                m = 0.f;
#pragma unroll
                for (int k = 1; k < 32; k++)
                    m += Wsm[(k - 1) * 31 + (i - 1)] * LWh[k * 32 + j];
            }
            Ms[idx] = m;
        }
        __syncthreads();
    }

    // ---- normalize + selu + Poincare + msg1 (fp32) + col absmax -------------
    const float alpha = 1.6732632423543772f;
    const float scale = 1.0507009873554805f;
    float amax = 0.f;

    for (int r = w * 8; r < w * 8 + 8; r++) {
        float s = sup[r * 33 + lane];

        float tt = s * s;
        float md = (lane == 0) ? -tt : tt;
#pragma unroll
        for (int o = 16; o; o >>= 1) md += __shfl_xor_sync(0xffffffffu, md, o);

        float denom = sqrtf(fmaxf(fabsf(md), 1e-8f));
        float xv    = s / denom;
        float x0    = __shfl_sync(0xffffffffu, xv, 0);

        float p = (lane == 0) ? 0.f : xv / (x0 + 1.f);
        p = (p > 0.f) ? scale * p : scale * alpha * (expf(p) - 1.f);

        float pn = p * p;
#pragma unroll
        for (int o = 16; o; o >>= 1) pn += __shfl_xor_sync(0xffffffffu, pn, o);

        float inv  = 1.f / (1.f - pn);
        float outv = (lane == 0) ? (1.f + pn) * inv : 2.f * p * inv;

        float a = 0.f;
#pragma unroll
        for (int k = 0; k < 32; k++)
            a = fmaf(__shfl_sync(0xffffffffu, outv, k), Ms[k * 32 + lane], a);
        sup2[r * 33 + lane] = a;
        amax = fmaxf(amax, fabsf(a));
    }

    __syncthreads();
    LWh[w * 32 + lane] = amax;
    __syncthreads();
    if (w == 0) {
        float m = LWh[lane];
#pragma unroll
        for (int i = 1; i < 8; i++) m = fmaxf(m, LWh[i * 32 + lane]);
        atomicMax(&g_colmax[lane], __float_as_uint(m));
    }

    // ---- coalesced transpose write of msg1 (fp32) into g_msgT1 ---------------
#pragma unroll
    for (int u = 0; u < 8; u++) {
        int idx = u * 256 + tid;       // 0..2047
        int n   = idx >> 6;            // 0..31
        int r   = idx & 63;            // 0..63
        g_msgT1[(size_t)n * NN + row0 + r] = sup2[r * 33 + n];
    }
}

// ---------------------------------------------------------------------------
// Kernel 3: quantize msg1 fp32 -> s8 with per-column scale 127/colmax.
// ---------------------------------------------------------------------------
__global__ __launch_bounds__(256)
void quant_msg_kernel() {
    __shared__ float scl[32];
    const int tid = threadIdx.x;
    if (tid < 32)
        scl[tid] = 127.f / fmaxf(__uint_as_float(g_colmax[tid]), 1e-30f);
    __syncthreads();

    const int idx = blockIdx.x * 256 + tid;   // 0..32767
    const int n   = idx >> 10;
    const int kg  = idx & 1023;
    const float s = scl[n];
    const float4* src = (const float4*)(g_msgT1 + (size_t)n * NN + kg * 16);
    uint32_t b[4];
#pragma unroll
    for (int q = 0; q < 4; q++) {
        float4 v = src[q];
        int q0 = __float2int_rn(v.x * s);
        int q1 = __float2int_rn(v.y * s);
        int q2 = __float2int_rn(v.z * s);
        int q3 = __float2int_rn(v.w * s);
        b[q] = (uint32_t)(q0 & 0xff) | ((uint32_t)(q1 & 0xff) << 8) |
               ((uint32_t)(q2 & 0xff) << 16) | ((uint32_t)(q3 & 0xff) << 24);
    }
    *reinterpret_cast<uint4*>(g_msg8 + (size_t)n * NN + kg * 16) =
        make_uint4(b[0], b[1], b[2], b[3]);
}

// ---------------------------------------------------------------------------
// Kernel 4 (gemm1): int8 TMA GEMM, BK=256/stage (64 sync points), 2 CTAs/SM,
//                   dequant + final epilogue.
// ---------------------------------------------------------------------------
__global__ __launch_bounds__(256)
void gemm1_kernel(const __grid_constant__ CUtensorMap tma_adj8,
                  const __grid_constant__ CUtensorMap tma_msg8,
                  float* __restrict__ outp) {
    extern __shared__ float dsm[];
    __shared__ alignas(8) uint64_t full_bar[STAGES1];
    __shared__ float cscale[32];

    const int tid  = threadIdx.x;
    const int lane = tid & 31;
    const int w    = tid >> 5;
    const int wm   = w & 3;
    const int wn   = w >> 2;
    const int g    = lane >> 2;
    const int c    = lane & 3;
    const int row0 = blockIdx.x * BM;

    const uint32_t sb    = smem_u32(dsm);
    const uint32_t base0 = (sb + 1023u) & ~1023u;
    char* tiles = (char*)dsm + (base0 - sb);

    if (tid == 0) {
#pragma unroll
        for (int s = 0; s < STAGES1; s++)
            mbar_init(smem_u32(&full_bar[s]), 1u);
    }
    if (tid < 32)
        cscale[tid] = fmaxf(__uint_as_float(g_colmax[tid]), 1e-30f) / (127.f * S_A);
    __syncthreads();
    if (tid == 0)
        asm volatile("fence.proxy.async.shared::cta;" ::: "memory");

    auto issue_stage = [&](int j) {
        const int  slot = j % STAGES1;
        const int  kt   = j * BK1;
        const uint32_t mb = smem_u32(&full_bar[slot]);
        const uint32_t db = base0 + (uint32_t)(slot * STAGE1_B);
        mbar_expect_tx(mb, (uint32_t)STAGE1_B);
        tma_load_2d(db,                          &tma_adj8, kt,       row0, mb);
        tma_load_2d(db + ADJ8_CH,                &tma_adj8, kt + 128, row0, mb);
        tma_load_2d(db + 2 * ADJ8_CH,            &tma_msg8, kt,       0,    mb);
        tma_load_2d(db + 2 * ADJ8_CH + MSG8_CH,  &tma_msg8, kt + 128, 0,    mb);
    };

    if (tid == 0) {
#pragma unroll
        for (int j = 0; j < STAGES1 - 1; j++) issue_stage(j);
    }

    int acc[2][4];
#pragma unroll
    for (int nt = 0; nt < 2; nt++)
#pragma unroll
        for (int j = 0; j < 4; j++) acc[nt][j] = 0;

    const int r0 = wm * 16 + g;
    const int r1 = r0 + 8;

    for (int it = 0; it < NITER1; it++) {
        const int slot = it % STAGES1;
        mbar_wait(smem_u32(&full_bar[slot]),
                  (uint32_t)(((it / STAGES1) & 1) ^ 0));

        const char* stg = tiles + slot * STAGE1_B;
#pragma unroll
        for (int j = 0; j < 8; j++) {             // 2 chunks x 4 k32-steps
            const char* adj = stg + (j >> 2) * ADJ8_CH;
            const char* msg = stg + 2 * ADJ8_CH + (j >> 2) * MSG8_CH;
            const int u0 = (j & 3) * 2;
            uint32_t a0 = *(const uint32_t*)(adj + r0 * 128 + ((u0    ) ^ g) * 16 + c * 4);
            uint32_t a1 = *(const uint32_t*)(adj + r1 * 128 + ((u0    ) ^ g) * 16 + c * 4);
            uint32_t a2 = *(const uint32_t*)(adj + r0 * 128 + ((u0 + 1) ^ g) * 16 + c * 4);
            uint32_t a3 = *(const uint32_t*)(adj + r1 * 128 + ((u0 + 1) ^ g) * 16 + c * 4);
#pragma unroll
            for (int nt = 0; nt < 2; nt++) {
                const int n = wn * 16 + nt * 8 + g;
                uint32_t b0 = *(const uint32_t*)(msg + n * 128 + ((u0    ) ^ g) * 16 + c * 4);
                uint32_t b1 = *(const uint32_t*)(msg + n * 128 + ((u0 + 1) ^ g) * 16 + c * 4);
                mma_s8(acc[nt], a0, a1, a2, a3, b0, b1);
            }
        }
        __syncthreads();

        const int nj = it + STAGES1 - 1;
        if (tid == 0 && nj < NITER1) issue_stage(nj);
    }

    // ---- dequant + epilogue: normalize + selu + Poincare -> output -----------
    float* sup = (float*)tiles;   // 64 x 33
#pragma unroll
    for (int nt = 0; nt < 2; nt++) {
        int cb = wn * 16 + nt * 8 + 2 * c;
        sup[r0 * 33 + cb]     = __int2float_rn(acc[nt][0]);
        sup[r0 * 33 + cb + 1] = __int2float_rn(acc[nt][1]);
        sup[r1 * 33 + cb]     = __int2float_rn(acc[nt][2]);
        sup[r1 * 33 + cb + 1] = __int2float_rn(acc[nt][3]);
    }
    __syncthreads();

    const float alpha = 1.6732632423543772f;
    const float scale = 1.0507009873554805f;

    for (int r = w * 8; r < w * 8 + 8; r++) {
        float s = sup[r * 33 + lane] * cscale[lane];

        float tt = s * s;
        float md = (lane == 0) ? -tt : tt;
#pragma unroll
        for (int o = 16; o; o >>= 1) md += __shfl_xor_sync(0xffffffffu, md, o);

        float denom = sqrtf(fmaxf(fabsf(md), 1e-8f));
        float xv    = s / denom;
        float x0    = __shfl_sync(0xffffffffu, xv, 0);

        float p = (lane == 0) ? 0.f : xv / (x0 + 1.f);
        p = (p > 0.f) ? scale * p : scale * alpha * (expf(p) - 1.f);

        float pn = p * p;
#pragma unroll
        for (int o = 16; o; o >>= 1) pn += __shfl_xor_sync(0xffffffffu, pn, o);

        float inv  = 1.f / (1.f - pn);
        float outv = (lane == 0) ? (1.f + pn) * inv : 2.f * p * inv;
        outp[(size_t)(row0 + r) * D + lane] = outv;
    }
}

// ---------------------------------------------------------------------------
// Host
// ---------------------------------------------------------------------------
typedef CUresult (*EncodeTiledFn)(
    CUtensorMap*, CUtensorMapDataType, cuuint32_t, void*,
    const cuuint64_t*, const cuuint64_t*, const cuuint32_t*, const cuuint32_t*,
    CUtensorMapInterleave, CUtensorMapSwizzle, CUtensorMapL2promotion,
    CUtensorMapFloatOOBfill);

static void encode_2d(EncodeTiledFn enc, CUtensorMap* map, void* ptr,
                      CUtensorMapDataType dt, uint32_t esz,
                      uint64_t d0, uint64_t d1, uint32_t b0, uint32_t b1,
                      CUtensorMapL2promotion promo) {
    cuuint64_t dims[2]    = {d0, d1};
    cuuint64_t strides[1] = {d0 * esz};
    cuuint32_t box[2]     = {b0, b1};
    cuuint32_t estr[2]    = {1, 1};
    enc(map, dt, 2, ptr, dims, strides, box, estr,
        CU_TENSOR_MAP_INTERLEAVE_NONE, CU_TENSOR_MAP_SWIZZLE_128B,
        promo, CU_TENSOR_MAP_FLOAT_OOB_FILL_NONE);
}

extern "C" void kernel_launch(void* const* d_in, const int* in_sizes, int n_in,
                              void* d_out, int out_size) {
    const float* node = (const float*)d_in[0];  // 16384 x 32
    const float* adj  = (const float*)d_in[1];  // 16384 x 16384
    const float* Ws   = (const float*)d_in[2];  // 2 x 31 x 31
    const float* Hs   = (const float*)d_in[3];  // 2 x 32
    float* out = (float*)d_out;                 // 16384 x 32

    void* fn = nullptr;
    cudaDriverEntryPointQueryResult qr;
    cudaGetDriverEntryPoint("cuTensorMapEncodeTiled", &fn, cudaEnableDefault, &qr);
    EncodeTiledFn enc = (EncodeTiledFn)fn;

    void *msgT_ptr = nullptr, *adj8_ptr = nullptr, *msg8_ptr = nullptr;
    cudaGetSymbolAddress(&msgT_ptr, g_msgT);
    cudaGetSymbolAddress(&adj8_ptr, g_adj8);
    cudaGetSymbolAddress(&msg8_ptr, g_msg8);

    CUtensorMap map_adj, map_msg, map_adj8, map_msg8;
    encode_2d(enc, &map_adj, (void*)adj, CU_TENSOR_MAP_DATA_TYPE_FLOAT32, 4,
              NN, NN, 32, BM, CU_TENSOR_MAP_L2_PROMOTION_L2_256B);
    encode_2d(enc, &map_msg, msgT_ptr, CU_TENSOR_MAP_DATA_TYPE_FLOAT32, 4,
              NN, D, 32, 32, CU_TENSOR_MAP_L2_PROMOTION_L2_128B);
    encode_2d(enc, &map_adj8, adj8_ptr, CU_TENSOR_MAP_DATA_TYPE_UINT8, 1,
              NN, NN, 128, BM, CU_TENSOR_MAP_L2_PROMOTION_L2_256B);
    encode_2d(enc, &map_msg8, msg8_ptr, CU_TENSOR_MAP_DATA_TYPE_UINT8, 1,
              NN, D, 128, 32, CU_TENSOR_MAP_L2_PROMOTION_L2_128B);

    cudaFuncSetAttribute(gemm0_kernel,
                         cudaFuncAttributeMaxDynamicSharedMemorySize, DYN_B);
    cudaFuncSetAttribute(gemm1_kernel,
                         cudaFuncAttributeMaxDynamicSharedMemorySize, DYN1_B);

    const int gemm_blocks = NN / BM;   // 256

    msgT0_kernel<<<NN / 128, 1024>>>(node, Ws, Hs);
    gemm0_kernel<<<gemm_blocks, 256, DYN_B>>>(map_adj, map_msg, Ws, Hs);
    quant_msg_kernel<<<128, 256>>>();
    gemm1_kernel<<<gemm_blocks, 256, DYN1_B>>>(map_adj8, map_msg8, out);
}

// round 16
// speedup vs baseline: 1.7719x; 1.7719x over previous
#include <cuda_runtime.h>
#include <cuda.h>
#include <math.h>
#include <stdint.h>

// SRBGCN: 2-layer hyperbolic GCN.  (R9 structure + lean msgT0; W-staging fixed.)
// support = adj(16384^2 fp32) @ msg(16384x32) per layer.
// TMA (SW128, L2-promo 256B on adj) 5-stage mbarrier pipeline -> mma.sync
// tf32 m16n8k8.  3 launches: msgT0, gemm0 (epilogue: normalize+selu+Poincare
// + M1 build + msg1^T), gemm1 (final output).

constexpr int NN     = 16384;
constexpr int D      = 32;
constexpr int BM     = 128;               // rows per CTA
constexpr int BK     = 64;                // k per stage (2 x 32-col TMA boxes)
constexpr int STAGES = 5;
constexpr int NITER  = NN / BK;           // 256
constexpr int ADJ_CH_B = 32 * BM * 4;     // 16384 B per 32-col adj chunk
constexpr int MSG_CH_B = 32 * 32 * 4;     // 4096 B per 32-col msg chunk
constexpr int STAGE_B  = 2 * ADJ_CH_B + 2 * MSG_CH_B;  // 40960
constexpr int DYN_B    = STAGES * STAGE_B + 1024;

// Scratch (static device arrays; no allocation allowed)
__device__ __align__(1024) float g_msgT[D * NN];   // msgT[n][k], k-contiguous

// ---------------------------------------------------------------------------
__device__ __forceinline__ uint32_t smem_u32(const void* p) {
    return (uint32_t)__cvta_generic_to_shared(p);
}
__device__ __forceinline__ void mma_tf32(float* c,
                                         uint32_t a0, uint32_t a1, uint32_t a2, uint32_t a3,
                                         uint32_t b0, uint32_t b1) {
    asm volatile(
        "mma.sync.aligned.m16n8k8.row.col.f32.tf32.tf32.f32 "
        "{%0,%1,%2,%3}, {%4,%5,%6,%7}, {%8,%9}, {%0,%1,%2,%3};"
        : "+f"(c[0]), "+f"(c[1]), "+f"(c[2]), "+f"(c[3])
        : "r"(a0), "r"(a1), "r"(a2), "r"(a3), "r"(b0), "r"(b1));
}
__device__ __forceinline__ float to_tf32_rna(float x) {
    uint32_t r;
    asm("cvt.rna.tf32.f32 %0, %1;" : "=r"(r) : "f"(x));
    return __uint_as_float(r);
}
__device__ __forceinline__ void mbar_init(uint32_t mbar, uint32_t cnt) {
    asm volatile("mbarrier.init.shared.b64 [%0], %1;" :: "r"(mbar), "r"(cnt) : "memory");
}
__device__ __forceinline__ void mbar_expect_tx(uint32_t mbar, uint32_t bytes) {
    asm volatile("mbarrier.arrive.expect_tx.shared.b64 _, [%0], %1;"
                 :: "r"(mbar), "r"(bytes) : "memory");
}
__device__ __forceinline__ void mbar_wait(uint32_t mbar, uint32_t parity) {
    asm volatile(
        "{\n\t.reg .pred P1;\n\t"
        "WAIT_LOOP_%=:\n\t"
        "mbarrier.try_wait.parity.shared.b64 P1, [%0], %1;\n\t"
        "@P1 bra.uni WAIT_DONE_%=;\n\t"
        "bra.uni WAIT_LOOP_%=;\n\t"
        "WAIT_DONE_%=:\n\t}"
        :: "r"(mbar), "r"(parity) : "memory");
}
__device__ __forceinline__ void tma_load_2d(uint32_t smem_dst, const void* map,
                                            int cx, int cy, uint32_t mbar) {
    asm volatile(
        "cp.async.bulk.tensor.2d.shared::cta.global.tile.mbarrier::complete_tx::bytes "
        "[%0], [%1, {%2, %3}], [%4];"
        :: "r"(smem_dst), "l"(map), "r"(cx), "r"(cy), "r"(mbar) : "memory");
}
__device__ __forceinline__ float lwh_elem(int i, int j, const float* h,
                                          float ch, float sh, float invn) {
    float ni = (i >= 1) ? h[i] * invn : 0.f;
    float nj = (j >= 1) ? h[j] * invn : 0.f;
    if (i == 0 && j == 0) return ch;
    if (i == 0)           return sh * nj;
    if (j == 0)           return sh * ni;
    return ((i == j) ? 1.f : 0.f) - (1.f - ch) * ni * nj;
}

// ---------------------------------------------------------------------------
// Kernel 1: msgT0 (lean). 256 blocks x 512 threads; block handles 64 rows.
// W0 staged in smem (FIXED: strided loop covers all 961 entries).
// ---------------------------------------------------------------------------
__global__ __launch_bounds__(512)
void msgT0_kernel(const float* __restrict__ node,
                  const float* __restrict__ Ws,
                  const float* __restrict__ Hs) {
    __shared__ float Wsm[961];
    __shared__ float hsm[32];
    __shared__ float sc[3];
    __shared__ float LWh[1024];
    __shared__ float Ms[1024];
    __shared__ float xs[64][33];
    __shared__ float ot[32][65];

    const int tid = threadIdx.x;
    const int r0  = blockIdx.x * 64;

    // stage W0 + h0 (961 entries over 512 threads: strided)
    for (int idx = tid; idx < 961; idx += 512) Wsm[idx] = Ws[idx];
    if (tid < 32) hsm[tid] = Hs[tid];
    // load x rows (coalesced float4): 2048 floats = 512 float4
    {
        int r  = tid >> 3;
        int c4 = tid & 7;
        float4 v = *reinterpret_cast<const float4*>(node + (size_t)(r0 + r) * D + c4 * 4);
        xs[r][c4 * 4 + 0] = v.x;
        xs[r][c4 * 4 + 1] = v.y;
        xs[r][c4 * 4 + 2] = v.z;
        xs[r][c4 * 4 + 3] = v.w;
    }
    __syncthreads();

    if (tid == 0) {
        float ss = 0.f;
        for (int t = 1; t < 32; t++) { float v = hsm[t]; ss += v * v; }
        sc[0] = coshf(hsm[0]);
        sc[1] = sinhf(hsm[0]);
        sc[2] = rsqrtf(ss + 1e-14f);
    }
    __syncthreads();

#pragma unroll
    for (int u = 0; u < 2; u++) {
        int idx = u * 512 + tid;
        LWh[idx] = lwh_elem(idx >> 5, idx & 31, hsm, sc[0], sc[1], sc[2]);
    }
    __syncthreads();

#pragma unroll
    for (int u = 0; u < 2; u++) {
        int idx = u * 512 + tid;
        int i = idx >> 5, j = idx & 31;
        float m;
        if (i == 0) {
            m = LWh[j];
        } else {
            m = 0.f;
#pragma unroll
            for (int k = 1; k < 32; k++)
                m += Wsm[(k - 1) * 31 + (i - 1)] * LWh[k * 32 + j];
        }
        Ms[idx] = m;
    }
    __syncthreads();

    // each thread: 4 consecutive rows, one n column
    {
        const int n  = tid & 31;
        const int rg = tid >> 5;          // 0..15 -> rows rg*4..rg*4+3
#pragma unroll
        for (int rr = 0; rr < 4; rr++) {
            const int r = rg * 4 + rr;
            float acc = 0.f;
#pragma unroll
            for (int k = 0; k < 32; k++)
                acc = fmaf(xs[r][k], Ms[k * 32 + n], acc);
            ot[n][r] = to_tf32_rna(acc);
        }
    }
    __syncthreads();

    // coalesced write: 2048 floats, idx = n*64 + r
#pragma unroll
    for (int u = 0; u < 4; u++) {
        int idx = u * 512 + tid;
        int n   = idx >> 6;
        int r   = idx & 63;
        g_msgT[(size_t)n * NN + r0 + r] = ot[n][r];
    }
}

// ---------------------------------------------------------------------------
// Kernel 2: TMA-fed tf32 mma.sync GEMM + fused epilogue (R9 config, unchanged).
// 256 threads = 8 warps; warp w owns rows [w*16, w*16+16), all 32 n-cols.
// ---------------------------------------------------------------------------
__global__ __launch_bounds__(256)
void gemm_epi_kernel(const __grid_constant__ CUtensorMap tma_adj,
                     const __grid_constant__ CUtensorMap tma_msg,
                     const float* __restrict__ Ws,
                     const float* __restrict__ Hs,
                     float* __restrict__ outp,
                     int layer) {
    extern __shared__ float dsm[];
    __shared__ alignas(8) uint64_t full_bar[STAGES];
    __shared__ float sc[3];

    const int tid  = threadIdx.x;
    const int lane = tid & 31;
    const int w    = tid >> 5;     // 0..7
    const int g    = lane >> 2;    // 0..7
    const int c    = lane & 3;     // 0..3
    const int row0 = blockIdx.x * BM;

    const uint32_t sb    = smem_u32(dsm);
    const uint32_t base0 = (sb + 1023u) & ~1023u;
    char* tiles = (char*)dsm + (base0 - sb);

    if (tid == 0) {
#pragma unroll
        for (int s = 0; s < STAGES; s++)
            mbar_init(smem_u32(&full_bar[s]), 1u);
    }
    __syncthreads();
    if (tid == 0)
        asm volatile("fence.proxy.async.shared::cta;" ::: "memory");

    auto issue_stage = [&](int j) {
        const int  slot = j % STAGES;
        const int  kt   = j * BK;
        const uint32_t mb = smem_u32(&full_bar[slot]);
        const uint32_t db = base0 + (uint32_t)(slot * STAGE_B);
        mbar_expect_tx(mb, (uint32_t)STAGE_B);
        tma_load_2d(db,                           &tma_adj, kt,      row0, mb);
        tma_load_2d(db + ADJ_CH_B,                &tma_adj, kt + 32, row0, mb);
        tma_load_2d(db + 2 * ADJ_CH_B,            &tma_msg, kt,      0,    mb);
        tma_load_2d(db + 2 * ADJ_CH_B + MSG_CH_B, &tma_msg, kt + 32, 0,    mb);
    };

    if (tid == 0) {
#pragma unroll
        for (int j = 0; j < STAGES - 1; j++) issue_stage(j);
    }

    float acc[4][4];
#pragma unroll
    for (int nt = 0; nt < 4; nt++)
#pragma unroll
        for (int j = 0; j < 4; j++) acc[nt][j] = 0.f;

    const int r0 = w * 16 + g;
    const int r1 = r0 + 8;

    for (int it = 0; it < NITER; it++) {
        const int slot = it % STAGES;
        mbar_wait(smem_u32(&full_bar[slot]), (uint32_t)((it / STAGES) & 1));

        const char* stg = tiles + slot * STAGE_B;
#pragma unroll
        for (int ks = 0; ks < 8; ks++) {
            const float* Ah = (const float*)(stg + (ks >> 2) * ADJ_CH_B);
            const float* Bh = (const float*)(stg + 2 * ADJ_CH_B + (ks >> 2) * MSG_CH_B);
            const int u0 = (ks & 3) * 2;

            uint32_t a0 = __float_as_uint(Ah[r0 * 32 + ((u0    ) ^ g) * 4 + c]);
            uint32_t a1 = __float_as_uint(Ah[r1 * 32 + ((u0    ) ^ g) * 4 + c]);
            uint32_t a2 = __float_as_uint(Ah[r0 * 32 + ((u0 + 1) ^ g) * 4 + c]);
            uint32_t a3 = __float_as_uint(Ah[r1 * 32 + ((u0 + 1) ^ g) * 4 + c]);
#pragma unroll
            for (int nt = 0; nt < 4; nt++) {
                const int n = nt * 8 + g;
                uint32_t b0 = __float_as_uint(Bh[n * 32 + ((u0    ) ^ g) * 4 + c]);
                uint32_t b1 = __float_as_uint(Bh[n * 32 + ((u0 + 1) ^ g) * 4 + c]);
                mma_tf32(acc[nt], a0, a1, a2, a3, b0, b1);
            }
        }
        __syncthreads();

        const int nj = it + STAGES - 1;
        if (tid == 0 && nj < NITER) issue_stage(nj);
    }

    // ---- epilogue smem (pipeline memory now free) ------------------------------
    float* sup  = (float*)tiles;          // 128 x 33
    float* sup2 = sup  + 128 * 33;        // 128 x 33 (W1 staging then msg1)
    float* LWh  = sup2 + 128 * 33;        // 32 x 32
    float* Ms   = LWh  + 1024;            // 32 x 32

#pragma unroll
    for (int nt = 0; nt < 4; nt++) {
        int cb = nt * 8 + 2 * c;
        sup[r0 * 33 + cb]     = acc[nt][0];
        sup[r0 * 33 + cb + 1] = acc[nt][1];
        sup[r1 * 33 + cb]     = acc[nt][2];
        sup[r1 * 33 + cb + 1] = acc[nt][3];
    }

    // ---- layer 0: build M1 (W1 staged in smem first) ---------------------------
    if (layer == 0) {
        const float* W1 = Ws + 31 * 31;
        const float* h1 = Hs + 32;
        float* Wsm = sup2;                 // temporary W1 staging (961 floats)
#pragma unroll
        for (int u = 0; u < 4; u++) {
            int idx = u * 256 + tid;
            if (idx < 961) Wsm[idx] = W1[idx];
        }
        if (tid == 0) {
            float ss = 0.f;
            for (int t = 1; t < 32; t++) { float v = h1[t]; ss += v * v; }
            sc[0] = coshf(h1[0]);
            sc[1] = sinhf(h1[0]);
            sc[2] = rsqrtf(ss + 1e-14f);
        }
        __syncthreads();
#pragma unroll
        for (int u = 0; u < 4; u++) {
            int idx = u * 256 + tid;
            LWh[idx] = lwh_elem(idx >> 5, idx & 31, h1, sc[0], sc[1], sc[2]);
        }
        __syncthreads();
#pragma unroll
        for (int u = 0; u < 4; u++) {
            int idx = u * 256 + tid;
            int i = idx >> 5, j = idx & 31;
            float m;
            if (i == 0) {
                m = LWh[j];
            } else {
                m = 0.f;
#pragma unroll
                for (int k = 1; k < 32; k++)
                    m += Wsm[(k - 1) * 31 + (i - 1)] * LWh[k * 32 + j];
            }
            Ms[idx] = m;
        }
        __syncthreads();
    } else {
        __syncwarp();
    }

    // ---- fused epilogue: normalize + selu + Poincare [+ msg1] ------------------
    const float alpha = 1.6732632423543772f;
    const float scale = 1.0507009873554805f;

    for (int r = w * 16; r < w * 16 + 16; r++) {
        float s = sup[r * 33 + lane];

        float tt = s * s;
        float md = (lane == 0) ? -tt : tt;
#pragma unroll
        for (int o = 16; o; o >>= 1) md += __shfl_xor_sync(0xffffffffu, md, o);

        float denom = sqrtf(fmaxf(fabsf(md), 1e-8f));
        float xv    = s / denom;
        float x0    = __shfl_sync(0xffffffffu, xv, 0);

        float p = (lane == 0) ? 0.f : xv / (x0 + 1.f);
        p = (p > 0.f) ? scale * p : scale * alpha * (expf(p) - 1.f);

        float pn = p * p;
#pragma unroll
        for (int o = 16; o; o >>= 1) pn += __shfl_xor_sync(0xffffffffu, pn, o);

        float inv  = 1.f / (1.f - pn);
        float outv = (lane == 0) ? (1.f + pn) * inv : 2.f * p * inv;

        if (layer == 1) {
            outp[(size_t)(row0 + r) * D + lane] = outv;
        } else {
            float a = 0.f;
#pragma unroll
            for (int k = 0; k < 32; k++)
                a = fmaf(__shfl_sync(0xffffffffu, outv, k), Ms[k * 32 + lane], a);
            sup2[r * 33 + lane] = to_tf32_rna(a);
        }
    }

    // ---- layer 0: coalesced transpose write of msg1 into g_msgT ----------------
    if (layer == 0) {
        __syncthreads();
#pragma unroll
        for (int u = 0; u < 16; u++) {
            int idx = u * 256 + tid;       // 0..4095
            int n   = idx >> 7;            // 0..31
            int r   = idx & 127;           // 0..127
            g_msgT[(size_t)n * NN + row0 + r] = sup2[r * 33 + n];
        }
    }
}

// ---------------------------------------------------------------------------
// Host: tensor-map creation via driver entry point (no -lcuda link needed).
// ---------------------------------------------------------------------------
typedef CUresult (*EncodeTiledFn)(
    CUtensorMap*, CUtensorMapDataType, cuuint32_t, void*,
    const cuuint64_t*, const cuuint64_t*, const cuuint32_t*, const cuuint32_t*,
    CUtensorMapInterleave, CUtensorMapSwizzle, CUtensorMapL2promotion,
    CUtensorMapFloatOOBfill);

static void encode_2d(EncodeTiledFn enc, CUtensorMap* map, void* ptr,
                      uint64_t d0, uint64_t d1, uint32_t b0, uint32_t b1,
                      CUtensorMapL2promotion promo) {
    cuuint64_t dims[2]    = {d0, d1};
    cuuint64_t strides[1] = {d0 * 4};
    cuuint32_t box[2]     = {b0, b1};
    cuuint32_t estr[2]    = {1, 1};
    enc(map, CU_TENSOR_MAP_DATA_TYPE_FLOAT32, 2, ptr, dims, strides, box, estr,
        CU_TENSOR_MAP_INTERLEAVE_NONE, CU_TENSOR_MAP_SWIZZLE_128B,
        promo, CU_TENSOR_MAP_FLOAT_OOB_FILL_NONE);
}

extern "C" void kernel_launch(void* const* d_in, const int* in_sizes, int n_in,
                              void* d_out, int out_size) {
    const float* node = (const float*)d_in[0];  // 16384 x 32
    const float* adj  = (const float*)d_in[1];  // 16384 x 16384
    const float* Ws   = (const float*)d_in[2];  // 2 x 31 x 31
    const float* Hs   = (const float*)d_in[3];  // 2 x 32
    float* out = (float*)d_out;                 // 16384 x 32

    void* fn = nullptr;
    cudaDriverEntryPointQueryResult qr;
    cudaGetDriverEntryPoint("cuTensorMapEncodeTiled", &fn, cudaEnableDefault, &qr);
    EncodeTiledFn enc = (EncodeTiledFn)fn;

    void* msgT_ptr = nullptr;
    cudaGetSymbolAddress(&msgT_ptr, g_msgT);

    CUtensorMap map_adj, map_msg;
    encode_2d(enc, &map_adj, (void*)adj, NN, NN, 32, BM,
              CU_TENSOR_MAP_L2_PROMOTION_L2_256B);
    encode_2d(enc, &map_msg, msgT_ptr,   NN, D,  32, 32,
              CU_TENSOR_MAP_L2_PROMOTION_L2_128B);

    cudaFuncSetAttribute(gemm_epi_kernel,
                         cudaFuncAttributeMaxDynamicSharedMemorySize, DYN_B);

    const int gemm_blocks = NN / BM;   // 128

    msgT0_kernel<<<NN / 64, 512>>>(node, Ws, Hs);
    gemm_epi_kernel<<<gemm_blocks, 256, DYN_B>>>(map_adj, map_msg, Ws, Hs, nullptr, 0);
    gemm_epi_kernel<<<gemm_blocks, 256, DYN_B>>>(map_adj, map_msg, Ws, Hs, out, 1);
}

// round 17
// speedup vs baseline: 1.7948x; 1.0129x over previous
#include <cuda_runtime.h>
#include <cuda.h>
#include <math.h>
#include <stdint.h>

// SRBGCN: 2-layer hyperbolic GCN.  (R15 + reversed-k in layer 1 for L2 reuse.)
// support = adj(16384^2 fp32) @ msg(16384x32) per layer.
// TMA (SW128, L2-promo 256B on adj) 5-stage mbarrier pipeline -> mma.sync
// tf32 m16n8k8.  Layer 1 iterates k HIGH->LOW so its first adj reads hit the
// L2 lines gemm0 touched last (~100+MB saved from DRAM).

constexpr int NN     = 16384;
constexpr int D      = 32;
constexpr int BM     = 128;               // rows per CTA
constexpr int BK     = 64;                // k per stage (2 x 32-col TMA boxes)
constexpr int STAGES = 5;
constexpr int NITER  = NN / BK;           // 256
constexpr int ADJ_CH_B = 32 * BM * 4;     // 16384 B per 32-col adj chunk
constexpr int MSG_CH_B = 32 * 32 * 4;     // 4096 B per 32-col msg chunk
constexpr int STAGE_B  = 2 * ADJ_CH_B + 2 * MSG_CH_B;  // 40960
constexpr int DYN_B    = STAGES * STAGE_B + 1024;

// Scratch (static device arrays; no allocation allowed)
__device__ __align__(1024) float g_msgT[D * NN];   // msgT[n][k], k-contiguous

// ---------------------------------------------------------------------------
__device__ __forceinline__ uint32_t smem_u32(const void* p) {
    return (uint32_t)__cvta_generic_to_shared(p);
}
__device__ __forceinline__ void mma_tf32(float* c,
                                         uint32_t a0, uint32_t a1, uint32_t a2, uint32_t a3,
                                         uint32_t b0, uint32_t b1) {
    asm volatile(
        "mma.sync.aligned.m16n8k8.row.col.f32.tf32.tf32.f32 "
        "{%0,%1,%2,%3}, {%4,%5,%6,%7}, {%8,%9}, {%0,%1,%2,%3};"
        : "+f"(c[0]), "+f"(c[1]), "+f"(c[2]), "+f"(c[3])
        : "r"(a0), "r"(a1), "r"(a2), "r"(a3), "r"(b0), "r"(b1));
}
__device__ __forceinline__ float to_tf32_rna(float x) {
    uint32_t r;
    asm("cvt.rna.tf32.f32 %0, %1;" : "=r"(r) : "f"(x));
    return __uint_as_float(r);
}
__device__ __forceinline__ void mbar_init(uint32_t mbar, uint32_t cnt) {
    asm volatile("mbarrier.init.shared.b64 [%0], %1;" :: "r"(mbar), "r"(cnt) : "memory");
}
__device__ __forceinline__ void mbar_expect_tx(uint32_t mbar, uint32_t bytes) {
    asm volatile("mbarrier.arrive.expect_tx.shared.b64 _, [%0], %1;"
                 :: "r"(mbar), "r"(bytes) : "memory");
}
__device__ __forceinline__ void mbar_wait(uint32_t mbar, uint32_t parity) {
    asm volatile(
        "{\n\t.reg .pred P1;\n\t"
        "WAIT_LOOP_%=:\n\t"
        "mbarrier.try_wait.parity.shared.b64 P1, [%0], %1;\n\t"
        "@P1 bra.uni WAIT_DONE_%=;\n\t"
        "bra.uni WAIT_LOOP_%=;\n\t"
        "WAIT_DONE_%=:\n\t}"
        :: "r"(mbar), "r"(parity) : "memory");
}
__device__ __forceinline__ void tma_load_2d(uint32_t smem_dst, const void* map,
                                            int cx, int cy, uint32_t mbar) {
    asm volatile(
        "cp.async.bulk.tensor.2d.shared::cta.global.tile.mbarrier::complete_tx::bytes "
        "[%0], [%1, {%2, %3}], [%4];"
        :: "r"(smem_dst), "l"(map), "r"(cx), "r"(cy), "r"(mbar) : "memory");
}
__device__ __forceinline__ float lwh_elem(int i, int j, const float* h,
                                          float ch, float sh, float invn) {
    float ni = (i >= 1) ? h[i] * invn : 0.f;
    float nj = (j >= 1) ? h[j] * invn : 0.f;
    if (i == 0 && j == 0) return ch;
    if (i == 0)           return sh * nj;
    if (j == 0)           return sh * ni;
    return ((i == j) ? 1.f : 0.f) - (1.f - ch) * ni * nj;
}

// ---------------------------------------------------------------------------
// Kernel 1: msgT0. 256 blocks x 512 threads; block handles 64 rows.
// ---------------------------------------------------------------------------
__global__ __launch_bounds__(512)
void msgT0_kernel(const float* __restrict__ node,
                  const float* __restrict__ Ws,
                  const float* __restrict__ Hs) {
    __shared__ float Wsm[961];
    __shared__ float hsm[32];
    __shared__ float sc[3];
    __shared__ float LWh[1024];
    __shared__ float Ms[1024];
    __shared__ float xs[64][33];
    __shared__ float ot[32][65];

    const int tid = threadIdx.x;
    const int r0  = blockIdx.x * 64;

    for (int idx = tid; idx < 961; idx += 512) Wsm[idx] = Ws[idx];
    if (tid < 32) hsm[tid] = Hs[tid];
    {
        int r  = tid >> 3;
        int c4 = tid & 7;
        float4 v = *reinterpret_cast<const float4*>(node + (size_t)(r0 + r) * D + c4 * 4);
        xs[r][c4 * 4 + 0] = v.x;
        xs[r][c4 * 4 + 1] = v.y;
        xs[r][c4 * 4 + 2] = v.z;
        xs[r][c4 * 4 + 3] = v.w;
    }
    __syncthreads();

    if (tid == 0) {
        float ss = 0.f;
        for (int t = 1; t < 32; t++) { float v = hsm[t]; ss += v * v; }
        sc[0] = coshf(hsm[0]);
        sc[1] = sinhf(hsm[0]);
        sc[2] = rsqrtf(ss + 1e-14f);
    }
    __syncthreads();

#pragma unroll
    for (int u = 0; u < 2; u++) {
        int idx = u * 512 + tid;
        LWh[idx] = lwh_elem(idx >> 5, idx & 31, hsm, sc[0], sc[1], sc[2]);
    }
    __syncthreads();

#pragma unroll
    for (int u = 0; u < 2; u++) {
        int idx = u * 512 + tid;
        int i = idx >> 5, j = idx & 31;
        float m;
        if (i == 0) {
            m = LWh[j];
        } else {
            m = 0.f;
#pragma unroll
            for (int k = 1; k < 32; k++)
                m += Wsm[(k - 1) * 31 + (i - 1)] * LWh[k * 32 + j];
        }
        Ms[idx] = m;
    }
    __syncthreads();

    {
        const int n  = tid & 31;
        const int rg = tid >> 5;
#pragma unroll
        for (int rr = 0; rr < 4; rr++) {
            const int r = rg * 4 + rr;
            float acc = 0.f;
#pragma unroll
            for (int k = 0; k < 32; k++)
                acc = fmaf(xs[r][k], Ms[k * 32 + n], acc);
            ot[n][r] = to_tf32_rna(acc);
        }
    }
    __syncthreads();

#pragma unroll
    for (int u = 0; u < 4; u++) {
        int idx = u * 512 + tid;
        int n   = idx >> 6;
        int r   = idx & 63;
        g_msgT[(size_t)n * NN + r0 + r] = ot[n][r];
    }
}

// ---------------------------------------------------------------------------
// Kernel 2: TMA-fed tf32 mma.sync GEMM + fused epilogue.
// layer==1 iterates k in REVERSE so its first reads hit gemm0's L2 tail.
// ---------------------------------------------------------------------------
__global__ __launch_bounds__(256)
void gemm_epi_kernel(const __grid_constant__ CUtensorMap tma_adj,
                     const __grid_constant__ CUtensorMap tma_msg,
                     const float* __restrict__ Ws,
                     const float* __restrict__ Hs,
                     float* __restrict__ outp,
                     int layer) {
    extern __shared__ float dsm[];
    __shared__ alignas(8) uint64_t full_bar[STAGES];
    __shared__ float sc[3];

    const int tid  = threadIdx.x;
    const int lane = tid & 31;
    const int w    = tid >> 5;     // 0..7
    const int g    = lane >> 2;    // 0..7
    const int c    = lane & 3;     // 0..3
    const int row0 = blockIdx.x * BM;

    const uint32_t sb    = smem_u32(dsm);
    const uint32_t base0 = (sb + 1023u) & ~1023u;
    char* tiles = (char*)dsm + (base0 - sb);

    if (tid == 0) {
#pragma unroll
        for (int s = 0; s < STAGES; s++)
            mbar_init(smem_u32(&full_bar[s]), 1u);
    }
    __syncthreads();
    if (tid == 0)
        asm volatile("fence.proxy.async.shared::cta;" ::: "memory");

    // k order: layer 0 forward, layer 1 reverse (L2 tail reuse)
    auto issue_stage = [&](int j) {
        const int  slot = j % STAGES;
        const int  kt   = (layer == 1) ? (NITER - 1 - j) * BK : j * BK;
        const uint32_t mb = smem_u32(&full_bar[slot]);
        const uint32_t db = base0 + (uint32_t)(slot * STAGE_B);
        mbar_expect_tx(mb, (uint32_t)STAGE_B);
        tma_load_2d(db,                           &tma_adj, kt,      row0, mb);
        tma_load_2d(db + ADJ_CH_B,                &tma_adj, kt + 32, row0, mb);
        tma_load_2d(db + 2 * ADJ_CH_B,            &tma_msg, kt,      0,    mb);
        tma_load_2d(db + 2 * ADJ_CH_B + MSG_CH_B, &tma_msg, kt + 32, 0,    mb);
    };

    if (tid == 0) {
#pragma unroll
        for (int j = 0; j < STAGES - 1; j++) issue_stage(j);
    }

    float acc[4][4];
#pragma unroll
    for (int nt = 0; nt < 4; nt++)
#pragma unroll
        for (int j = 0; j < 4; j++) acc[nt][j] = 0.f;

    const int r0 = w * 16 + g;
    const int r1 = r0 + 8;

    for (int it = 0; it < NITER; it++) {
        const int slot = it % STAGES;
        mbar_wait(smem_u32(&full_bar[slot]), (uint32_t)((it / STAGES) & 1));

        const char* stg = tiles + slot * STAGE_B;
#pragma unroll
        for (int ks = 0; ks < 8; ks++) {
            const float* Ah = (const float*)(stg + (ks >> 2) * ADJ_CH_B);
            const float* Bh = (const float*)(stg + 2 * ADJ_CH_B + (ks >> 2) * MSG_CH_B);
            const int u0 = (ks & 3) * 2;

            uint32_t a0 = __float_as_uint(Ah[r0 * 32 + ((u0    ) ^ g) * 4 + c]);
            uint32_t a1 = __float_as_uint(Ah[r1 * 32 + ((u0    ) ^ g) * 4 + c]);
            uint32_t a2 = __float_as_uint(Ah[r0 * 32 + ((u0 + 1) ^ g) * 4 + c]);
            uint32_t a3 = __float_as_uint(Ah[r1 * 32 + ((u0 + 1) ^ g) * 4 + c]);
#pragma unroll
            for (int nt = 0; nt < 4; nt++) {
                const int n = nt * 8 + g;
                uint32_t b0 = __float_as_uint(Bh[n * 32 + ((u0    ) ^ g) * 4 + c]);
                uint32_t b1 = __float_as_uint(Bh[n * 32 + ((u0 + 1) ^ g) * 4 + c]);
                mma_tf32(acc[nt], a0, a1, a2, a3, b0, b1);
            }
        }
        __syncthreads();

        const int nj = it + STAGES - 1;
        if (tid == 0 && nj < NITER) issue_stage(nj);
    }

    // ---- epilogue smem (pipeline memory now free) ------------------------------
    float* sup  = (float*)tiles;          // 128 x 33
    float* sup2 = sup  + 128 * 33;        // 128 x 33 (W1 staging then msg1)
    float* LWh  = sup2 + 128 * 33;        // 32 x 32
    float* Ms   = LWh  + 1024;            // 32 x 32

#pragma unroll
    for (int nt = 0; nt < 4; nt++) {
        int cb = nt * 8 + 2 * c;
        sup[r0 * 33 + cb]     = acc[nt][0];
        sup[r0 * 33 + cb + 1] = acc[nt][1];
        sup[r1 * 33 + cb]     = acc[nt][2];
        sup[r1 * 33 + cb + 1] = acc[nt][3];
    }

    // ---- layer 0: build M1 (W1 staged in smem first) ---------------------------
    if (layer == 0) {
        const float* W1 = Ws + 31 * 31;
        const float* h1 = Hs + 32;
        float* Wsm = sup2;
#pragma unroll
        for (int u = 0; u < 4; u++) {
            int idx = u * 256 + tid;
            if (idx < 961) Wsm[idx] = W1[idx];
        }
        if (tid == 0) {
            float ss = 0.f;
            for (int t = 1; t < 32; t++) { float v = h1[t]; ss += v * v; }
            sc[0] = coshf(h1[0]);
            sc[1] = sinhf(h1[0]);
            sc[2] = rsqrtf(ss + 1e-14f);
        }
        __syncthreads();
#pragma unroll
        for (int u = 0; u < 4; u++) {
            int idx = u * 256 + tid;
            LWh[idx] = lwh_elem(idx >> 5, idx & 31, h1, sc[0], sc[1], sc[2]);
        }
        __syncthreads();
#pragma unroll
        for (int u = 0; u < 4; u++) {
            int idx = u * 256 + tid;
            int i = idx >> 5, j = idx & 31;
            float m;
            if (i == 0) {
                m = LWh[j];
            } else {
                m = 0.f;
#pragma unroll
                for (int k = 1; k < 32; k++)
                    m += Wsm[(k - 1) * 31 + (i - 1)] * LWh[k * 32 + j];
            }
            Ms[idx] = m;
        }
        __syncthreads();
    } else {
        __syncwarp();
    }

    // ---- fused epilogue: normalize + selu + Poincare [+ msg1] ------------------
    const float alpha = 1.6732632423543772f;
    const float scale = 1.0507009873554805f;

    for (int r = w * 16; r < w * 16 + 16; r++) {
        float s = sup[r * 33 + lane];

        float tt = s * s;
        float md = (lane == 0) ? -tt : tt;
#pragma unroll
        for (int o = 16; o; o >>= 1) md += __shfl_xor_sync(0xffffffffu, md, o);

        float denom = sqrtf(fmaxf(fabsf(md), 1e-8f));
        float xv    = s / denom;
        float x0    = __shfl_sync(0xffffffffu, xv, 0);

        float p = (lane == 0) ? 0.f : xv / (x0 + 1.f);
        p = (p > 0.f) ? scale * p : scale * alpha * (expf(p) - 1.f);

        float pn = p * p;
#pragma unroll
        for (int o = 16; o; o >>= 1) pn += __shfl_xor_sync(0xffffffffu, pn, o);

        float inv  = 1.f / (1.f - pn);
        float outv = (lane == 0) ? (1.f + pn) * inv : 2.f * p * inv;

        if (layer == 1) {
            outp[(size_t)(row0 + r) * D + lane] = outv;
        } else {
            float a = 0.f;
#pragma unroll
            for (int k = 0; k < 32; k++)
                a = fmaf(__shfl_sync(0xffffffffu, outv, k), Ms[k * 32 + lane], a);
            sup2[r * 33 + lane] = to_tf32_rna(a);
        }
    }

    // ---- layer 0: coalesced transpose write of msg1 into g_msgT ----------------
    if (layer == 0) {
        __syncthreads();
#pragma unroll
        for (int u = 0; u < 16; u++) {
            int idx = u * 256 + tid;       // 0..4095
            int n   = idx >> 7;            // 0..31
            int r   = idx & 127;           // 0..127
            g_msgT[(size_t)n * NN + row0 + r] = sup2[r * 33 + n];
        }
    }
}

// ---------------------------------------------------------------------------
// Host: tensor-map creation via driver entry point (no -lcuda link needed).
// ---------------------------------------------------------------------------
typedef CUresult (*EncodeTiledFn)(
    CUtensorMap*, CUtensorMapDataType, cuuint32_t, void*,
    const cuuint64_t*, const cuuint64_t*, const cuuint32_t*, const cuuint32_t*,
    CUtensorMapInterleave, CUtensorMapSwizzle, CUtensorMapL2promotion,
    CUtensorMapFloatOOBfill);

static void encode_2d(EncodeTiledFn enc, CUtensorMap* map, void* ptr,
                      uint64_t d0, uint64_t d1, uint32_t b0, uint32_t b1,
                      CUtensorMapL2promotion promo) {
    cuuint64_t dims[2]    = {d0, d1};
    cuuint64_t strides[1] = {d0 * 4};
    cuuint32_t box[2]     = {b0, b1};
    cuuint32_t estr[2]    = {1, 1};
    enc(map, CU_TENSOR_MAP_DATA_TYPE_FLOAT32, 2, ptr, dims, strides, box, estr,
        CU_TENSOR_MAP_INTERLEAVE_NONE, CU_TENSOR_MAP_SWIZZLE_128B,
        promo, CU_TENSOR_MAP_FLOAT_OOB_FILL_NONE);
}

extern "C" void kernel_launch(void* const* d_in, const int* in_sizes, int n_in,
                              void* d_out, int out_size) {
    const float* node = (const float*)d_in[0];  // 16384 x 32
    const float* adj  = (const float*)d_in[1];  // 16384 x 16384
    const float* Ws   = (const float*)d_in[2];  // 2 x 31 x 31
    const float* Hs   = (const float*)d_in[3];  // 2 x 32
    float* out = (float*)d_out;                 // 16384 x 32

    void* fn = nullptr;
    cudaDriverEntryPointQueryResult qr;
    cudaGetDriverEntryPoint("cuTensorMapEncodeTiled", &fn, cudaEnableDefault, &qr);
    EncodeTiledFn enc = (EncodeTiledFn)fn;

    void* msgT_ptr = nullptr;
    cudaGetSymbolAddress(&msgT_ptr, g_msgT);

    CUtensorMap map_adj, map_msg;
    encode_2d(enc, &map_adj, (void*)adj, NN, NN, 32, BM,
              CU_TENSOR_MAP_L2_PROMOTION_L2_256B);
    encode_2d(enc, &map_msg, msgT_ptr,   NN, D,  32, 32,
              CU_TENSOR_MAP_L2_PROMOTION_L2_128B);

    cudaFuncSetAttribute(gemm_epi_kernel,
                         cudaFuncAttributeMaxDynamicSharedMemorySize, DYN_B);

    const int gemm_blocks = NN / BM;   // 128

    msgT0_kernel<<<NN / 64, 512>>>(node, Ws, Hs);
    gemm_epi_kernel<<<gemm_blocks, 256, DYN_B>>>(map_adj, map_msg, Ws, Hs, nullptr, 0);
    gemm_epi_kernel<<<gemm_blocks, 256, DYN_B>>>(map_adj, map_msg, Ws, Hs, out, 1);
}